// round 10
// baseline (speedup 1.0000x reference)
#include <cuda_runtime.h>
#include <math.h>

#define NN    68
#define TPB   192
#define TILE  32

typedef unsigned long long u64;

// Packed f32x2 ops (Blackwell) — only reachable via PTX.
__device__ __forceinline__ u64 ffma2(u64 a, u64 b, u64 c) {
    u64 d;
    asm("fma.rn.f32x2 %0, %1, %2, %3;" : "=l"(d) : "l"(a), "l"(b), "l"(c));
    return d;
}
__device__ __forceinline__ u64 fadd2(u64 a, u64 b) {
    u64 d;
    asm("add.rn.f32x2 %0, %1, %2;" : "=l"(d) : "l"(a), "l"(b));
    return d;
}
__device__ __forceinline__ void unpk(u64 v, float &x, float &y) {
    asm("mov.b64 {%0, %1}, %2;" : "=f"(x), "=f"(y) : "l"(v));
}
__device__ __forceinline__ u64 pack2(float x, float y) {
    u64 v;
    asm("mov.b64 %0, {%1, %2};" : "=l"(v) : "f"(x), "f"(y));
    return v;
}
// MUFU fast paths (~1e-7 rel err; validated 1.31e-6 final over 200k steps).
__device__ __forceinline__ float ex2a(float x) {
    float y; asm("ex2.approx.f32 %0, %1;" : "=f"(y) : "f"(x)); return y;
}
__device__ __forceinline__ float rcpa(float x) {
    float y; asm("rcp.approx.f32 %0, %1;" : "=f"(y) : "f"(x)); return y;
}

__global__ __launch_bounds__(TPB, 1)
void nmm_kernel(const float* __restrict__ params,
                const float* __restrict__ C,
                const float* __restrict__ y0,
                float* __restrict__ out,
                int num_steps)
{
    // 4-slot ring of delayed E; 72 cols (pads 68..71 zeroed once, coeffs 0).
    __shared__ __align__(16) float ebuf[4][72];
    // Ping-pong output staging; 34-col pad => 8B-aligned u64 pair stores.
    __shared__ __align__(16) float outbuf[2][NN][TILE + 2];

    const int tid  = threadIdx.x;
    const int lane = tid & 31;
    const int wid  = tid >> 5;
    // COLUMN-SPLIT layout: 2 lanes per row. Warps 0-4 compute; warp 5 flushes.
    const int row   = tid >> 1;                    // 0..95 (>=68 redundant)
    const int half  = tid & 1;                     // which 36-column half
    const int rload = (row < NN) ? row : (NN - 1); // clamp for global reads
    const bool wr   = (half == 0) && (row < NN);   // this lane publishes
    const int cofs  = half * 36;                   // my column base in ebuf row

    const float tau_e = params[0], tau_i = params[1];
    const float c1 = params[2], c2 = params[3], c3 = params[4], c4 = params[5];
    const float c5 = params[6], Pp = params[7], kE = params[8], kI = params[9];
    const float inv_te = 1.0f / tau_e;
    const float inv_ti = 1.0f / tau_i;
    const float ce = 1.0f - inv_te;
    const float ci = 1.0f - inv_ti;

    const float LOG2E = 1.4426950408889634f;
    const float AE = 1.3f, THR_E = 4.0f;
    const float AI = 2.0f, THR_I = 3.7f;
    const float aeL = AE * LOG2E;
    const float aiL = AI * LOG2E;
    const float S0E = 1.0f / (1.0f + expf(AE * THR_E));
    const float S0I = 1.0f / (1.0f + expf(AI * THR_I));

    const float cE0   = aeL * (THR_E - Pp);
    const float mEc1  = -aeL * c1;
    const float pEc2  =  aeL * c2;
    const float kconn = -aeL * c5;        // folded into crow below
    const float cI0   = aiL * THR_I;
    const float mIc3  = -aiL * c3;
    const float pIc4  =  aiL * c4;

    float E = 0.0f, I = 0.0f;
    u64 crow[18];                         // my 36 cols: {kconn*C, kconn*C} pairs

    if (wid < 5) {
        E = y0[rload];
        I = y0[NN + rload];
        #pragma unroll
        for (int jj = 0; jj < 9; jj++) {
            const int c0 = cofs + jj * 4;
            const float v0 = (c0 + 0 < NN) ? kconn * C[rload * NN + c0 + 0] : 0.0f;
            const float v1 = (c0 + 1 < NN) ? kconn * C[rload * NN + c0 + 1] : 0.0f;
            const float v2 = (c0 + 2 < NN) ? kconn * C[rload * NN + c0 + 2] : 0.0f;
            const float v3 = (c0 + 3 < NN) ? kconn * C[rload * NN + c0 + 3] : 0.0f;
            crow[2 * jj]     = pack2(v0, v1);
            crow[2 * jj + 1] = pack2(v2, v3);
        }
        if (wr) {
            ebuf[3][row] = E;             // E_{-1} := E_0 (reference carry)
            ebuf[0][row] = E;             // E_0
        }
    }
    if (wid == 5 && lane < 4) {           // zero pads in ALL slots, once
        ebuf[0][NN + lane] = 0.0f;
        ebuf[1][NN + lane] = 0.0f;
        ebuf[2][NN + lane] = 0.0f;
        ebuf[3][NN + lane] = 0.0f;
    }
    __syncthreads();

    // Warp-5 flush of one step's column window (17 rows x 4 windows/tile).
#define FLUSH_STEP(X)                                                          \
    {                                                                          \
        const int fk = (X) & 31;                                               \
        if (fk < 4 && (X) >= 32) {                                             \
            const int fb    = ((X) >> 5) - 1;                                  \
            const int ftile = fb & 1;                                          \
            const int fbase = fb << 5;                                         \
            _Pragma("unroll")                                                  \
            for (int i = 0; i < 17; i++) {                                     \
                const int rw = fk * 17 + i;                                    \
                out[rw * num_steps + fbase + lane] = outbuf[ftile][rw][lane];  \
            }                                                                  \
        }                                                                      \
    }

    // Half-row matvec: 9 ulonglong2 loads, 18 FFMA2, 4 chains.
#define HALF_MV(SLOT, R0, R1, R2, R3)                                          \
    {                                                                          \
        const ulonglong2* eb =                                                 \
            reinterpret_cast<const ulonglong2*>(&ebuf[SLOT][cofs]);            \
        _Pragma("unroll")                                                      \
        for (int j = 0; j < 9; j++) {                                          \
            ulonglong2 e = eb[j];                                              \
            if (j & 1) {                                                       \
                R2 = ffma2(crow[2 * j],     e.x, R2);                          \
                R3 = ffma2(crow[2 * j + 1], e.y, R3);                          \
            } else {                                                           \
                R0 = ffma2(crow[2 * j],     e.x, R0);                          \
                R1 = ffma2(crow[2 * j + 1], e.y, R1);                          \
            }                                                                  \
        }                                                                      \
    }

    // ---- one block = 2 Euler steps (S even), ONE barrier ----
#define BLOCK(PAR, S)                                                          \
    {                                                                          \
        if (wid < 5) {                                                         \
            /* pointwise-A (scalar, R7-validated form) */                      \
            const float gEa = inv_te * (kE - E);                               \
            const float hEa = fmaf(-gEa, S0E, E * ce);                         \
            const float gIa = inv_ti * (kI - I);                               \
            const float hIa = fmaf(-gIa, S0I, I * ci);                         \
            const float base_ea = fmaf(mEc1, E, fmaf(pEc2, I, cE0));           \
            const float argIa   = fmaf(mIc3, E, fmaf(pIc4, I, cI0));           \
            const float sIa = rcpa(1.0f + ex2a(argIa));                        \
            const float Ina = fmaf(gIa, sIa, hIa);                             \
            /* matvec-A over E_{S-1}: my half-row */                           \
            u64 a0 = 0ull, a1 = 0ull, a2 = 0ull, a3 = 0ull;                    \
            HALF_MV(((PAR) + 3) & 3, a0, a1, a2, a3)                           \
            u64 sv = fadd2(fadd2(a0, a1), fadd2(a2, a3));                      \
            float sx, sy;                                                      \
            unpk(sv, sx, sy);                                                  \
            const float pA = sx + sy;                                          \
            const float qA = __shfl_xor_sync(0xffffffffu, pA, 1, 32);          \
            const float argEa = (pA + qA) + base_ea;                           \
            const float sEa   = rcpa(1.0f + ex2a(argEa));                      \
            /* matvec-B over E_S — fills tail-A's MUFU shadow */               \
            u64 b0 = 0ull, b1 = 0ull, b2 = 0ull, b3 = 0ull;                    \
            HALF_MV((PAR), b0, b1, b2, b3)                                     \
            /* finish A */                                                     \
            const float Ena = fmaf(gEa, sEa, hEa);                             \
            if (wr) ebuf[((PAR) + 1) & 3][row] = Ena;  /* publish E_{S+1} */   \
            /* pointwise-B + tail-B */                                         \
            const float gEb = inv_te * (kE - Ena);                             \
            const float hEb = fmaf(-gEb, S0E, Ena * ce);                       \
            const float gIb = inv_ti * (kI - Ina);                             \
            const float hIb = fmaf(-gIb, S0I, Ina * ci);                       \
            const float base_eb = fmaf(mEc1, Ena, fmaf(pEc2, Ina, cE0));       \
            const float argIb   = fmaf(mIc3, Ena, fmaf(pIc4, Ina, cI0));       \
            const float sIb = rcpa(1.0f + ex2a(argIb));                        \
            const float Inb = fmaf(gIb, sIb, hIb);                             \
            u64 tv = fadd2(fadd2(b0, b1), fadd2(b2, b3));                      \
            float tx, ty;                                                      \
            unpk(tv, tx, ty);                                                  \
            const float pB = tx + ty;                                          \
            const float qB = __shfl_xor_sync(0xffffffffu, pB, 1, 32);          \
            const float argEb = (pB + qB) + base_eb;                           \
            const float sEb   = rcpa(1.0f + ex2a(argEb));                      \
            const float Enb   = fmaf(gEb, sEb, hEb);                           \
            if (wr) {                                                          \
                ebuf[((PAR) + 2) & 3][row] = Enb;      /* publish E_{S+2} */   \
                *reinterpret_cast<u64*>(                                       \
                    &outbuf[((S) >> 5) & 1][row][(S) & (TILE - 1)]) =          \
                    pack2(Ena - Ina, Enb - Inb);                               \
            }                                                                  \
            E = Enb;                                                           \
            I = Inb;                                                           \
        }                                                                      \
        __syncthreads();                                                       \
        if (wid == 5) {                                                        \
            FLUSH_STEP(S)                                                      \
            FLUSH_STEP((S) + 1)                                                \
        }                                                                      \
    }

    int s = 0;
    for (; s + 4 <= num_steps; s += 4) {
        BLOCK(0, s)
        BLOCK(2, s + 2)
    }
    if (s + 2 <= num_steps) {   // here s % 4 == 0
        BLOCK(0, s)
        s += 2;
    }
    if (s < num_steps) {        // odd leftover step (generic, runtime slot)
        if (wid < 5) {
            const float gE = inv_te * (kE - E);
            const float hE = fmaf(-gE, S0E, E * ce);
            const float gI = inv_ti * (kI - I);
            const float hI = fmaf(-gI, S0I, I * ci);
            const float base_e = fmaf(mEc1, E, fmaf(pEc2, I, cE0));
            const float argI   = fmaf(mIc3, E, fmaf(pIc4, I, cI0));
            const float sIv = rcpa(1.0f + ex2a(argI));
            const float In  = fmaf(gI, sIv, hI);
            u64 a0 = 0ull, a1 = 0ull, a2 = 0ull, a3 = 0ull;
            HALF_MV((s + 3) & 3, a0, a1, a2, a3)
            u64 sv = fadd2(fadd2(a0, a1), fadd2(a2, a3));
            float sx, sy;
            unpk(sv, sx, sy);
            const float pA = sx + sy;
            const float qA = __shfl_xor_sync(0xffffffffu, pA, 1, 32);
            const float argE = (pA + qA) + base_e;
            const float sEv  = rcpa(1.0f + ex2a(argE));
            const float En   = fmaf(gE, sEv, hE);
            if (wr) outbuf[(s >> 5) & 1][row][s & (TILE - 1)] = En - In;
        }
        __syncthreads();
        s++;
    }
#undef BLOCK
#undef HALF_MV
#undef FLUSH_STEP

    // Epilogue: flush tiles the in-loop warp-5 flush couldn't cover
    // (last complete tile whose flush window fell off the end + partial tile).
    int start;
    if (num_steps < 36) start = 0;
    else                start = (((num_steps - 36) >> 5) << 5) + 32;
    for (int tb = start; tb < num_steps; tb += 32) {
        const int ftile = (tb >> 5) & 1;
        const int cnt   = num_steps - tb < 32 ? num_steps - tb : 32;
        for (int rw = wid; rw < NN; rw += 6)
            if (lane < cnt)
                out[rw * num_steps + tb + lane] = outbuf[ftile][rw][lane];
    }
}

extern "C" void kernel_launch(void* const* d_in, const int* in_sizes, int n_in,
                              void* d_out, int out_size)
{
    const float* params = (const float*)d_in[0];
    const float* Cjk    = (const float*)d_in[1];
    const float* y0     = (const float*)d_in[2];
    // d_in[3] = Djk: unused by the reference computation.
    float* out = (float*)d_out;
    const int num_steps = out_size / NN;   // out is (N=68, num_steps)
    nmm_kernel<<<1, TPB>>>(params, Cjk, y0, out, num_steps);
}

// round 11
// speedup vs baseline: 1.1577x; 1.1577x over previous
#include <cuda_runtime.h>
#include <math.h>

#define NN    68
#define TPB   128
#define TILE  32

typedef unsigned long long u64;

// Packed f32x2 ops (Blackwell) — only reachable via PTX.
__device__ __forceinline__ u64 ffma2(u64 a, u64 b, u64 c) {
    u64 d;
    asm("fma.rn.f32x2 %0, %1, %2, %3;" : "=l"(d) : "l"(a), "l"(b), "l"(c));
    return d;
}
__device__ __forceinline__ u64 fadd2(u64 a, u64 b) {
    u64 d;
    asm("add.rn.f32x2 %0, %1, %2;" : "=l"(d) : "l"(a), "l"(b));
    return d;
}
__device__ __forceinline__ u64 fmul2(u64 a, u64 b) {
    u64 d;
    asm("mul.rn.f32x2 %0, %1, %2;" : "=l"(d) : "l"(a), "l"(b));
    return d;
}
__device__ __forceinline__ void unpk(u64 v, float &x, float &y) {
    asm("mov.b64 {%0, %1}, %2;" : "=f"(x), "=f"(y) : "l"(v));
}
__device__ __forceinline__ u64 pack2(float x, float y) {
    u64 v;
    asm("mov.b64 %0, {%1, %2};" : "=l"(v) : "f"(x), "f"(y));
    return v;
}
// MUFU fast paths (~1e-7 rel err; validated 1.31e-6 final over 200k steps).
__device__ __forceinline__ float ex2a(float x) {
    float y; asm("ex2.approx.f32 %0, %1;" : "=f"(y) : "f"(x)); return y;
}
__device__ __forceinline__ float rcpa(float x) {
    float y; asm("rcp.approx.f32 %0, %1;" : "=f"(y) : "f"(x)); return y;
}

__global__ __launch_bounds__(TPB, 1)
void nmm_kernel(const float* __restrict__ params,
                const float* __restrict__ C,
                const float* __restrict__ y0,
                float* __restrict__ out,
                int num_steps)
{
    // 4-slot ring: E_t lives in ebuf[t & 3]. Block k (steps 2k, 2k+1) reads
    // E_{2k-1} (slot (P+3)&3) and E_{2k} (slot P); writes E_{2k+1}, E_{2k+2}
    // into (P+1)&3, (P+2)&3. One barrier per block orders all crossings.
    __shared__ __align__(16) float ebuf[4][72];
    // Ping-pong output staging; rows padded to 34 floats => 8B-aligned
    // STS.64 pair stores; flush reads stay row-contiguous (conflict-free).
    __shared__ __align__(16) float outbuf[2][NN][TILE + 2];

    const int tid  = threadIdx.x;
    const int lane = tid & 31;
    const int wid  = tid >> 5;
    const int r    = tid;                 // row owned by this thread (r < 68)

    const float tau_e = params[0], tau_i = params[1];
    const float c1 = params[2], c2 = params[3], c3 = params[4], c4 = params[5];
    const float c5 = params[6], Pp = params[7], kE = params[8], kI = params[9];
    const float inv_te = 1.0f / tau_e;
    const float inv_ti = 1.0f / tau_i;
    const float ce = 1.0f - inv_te;
    const float ci = 1.0f - inv_ti;

    const float LOG2E = 1.4426950408889634f;
    const float AE = 1.3f, THR_E = 4.0f;
    const float AI = 2.0f, THR_I = 3.7f;
    const float aeL = AE * LOG2E;
    const float aiL = AI * LOG2E;
    const float S0E = 1.0f / (1.0f + expf(AE * THR_E));
    const float S0I = 1.0f / (1.0f + expf(AI * THR_I));

    const float cE0   = aeL * (THR_E - Pp);
    const float mEc1  = -aeL * c1;
    const float pEc2  =  aeL * c2;
    const float kconn = -aeL * c5;        // folded into crow below
    const float cI0   = aiL * THR_I;
    const float mIc3  = -aiL * c3;
    const float pIc4  =  aiL * c4;

    float E = 0.0f, I = 0.0f;
    u64 crow[34];                         // kconn * C[r,:], packed f32x2

    if (r < NN) {
        E = y0[r];
        I = y0[NN + r];
        ebuf[3][r] = E;                   // E_{-1} := E_0 (reference carry)
        ebuf[0][r] = E;                   // E_0
        const ulonglong2* cp = reinterpret_cast<const ulonglong2*>(C + r * NN);
        const u64 k2 = pack2(kconn, kconn);
        #pragma unroll
        for (int j = 0; j < 17; j++) {
            ulonglong2 c = cp[j];
            crow[2 * j]     = fmul2(c.x, k2);
            crow[2 * j + 1] = fmul2(c.y, k2);
        }
    }
    __syncthreads();

    // Warp-3 flush of one step's column window (17 rows x 4 windows/tile).
#define FLUSH_STEP(X)                                                          \
    {                                                                          \
        const int fk = (X) & 31;                                               \
        if (fk < 4 && (X) >= 32) {                                             \
            const int fb    = ((X) >> 5) - 1;                                  \
            const int ftile = fb & 1;                                          \
            const int fbase = fb << 5;                                         \
            _Pragma("unroll")                                                  \
            for (int i = 0; i < 17; i++) {                                     \
                const int row = fk * 17 + i;                                   \
                out[row * num_steps + fbase + lane] = outbuf[ftile][row][lane];\
            }                                                                  \
        }                                                                      \
    }

    // ---- one block = 2 Euler steps (S even), ONE barrier ----
    // PAR = S % 4 (compile-time 0 or 2 in the main loop).
    // Critical chain after reduce-A:
    //   ex2 -> fadd -> rcp -> sEa -> 1 FMA (argEb = K2e*sEa + K1e)
    //   -> ex2 -> fadd -> rcp -> sEb -> fma(Enb) -> STS
    // Everything else (Ena, gEb/hEb, whole I-b path) hangs OFF this chain.
#define BLOCK(PAR, S)                                                          \
    {                                                                          \
        if (r < NN) {                                                          \
            /* pointwise-A from state at iteration S (all early) */            \
            const float gEa = inv_te * (kE - E);                               \
            const float hEa = fmaf(-gEa, S0E, E * ce);                         \
            const float gIa = inv_ti * (kI - I);                               \
            const float hIa = fmaf(-gIa, S0I, I * ci);                         \
            const float base_ea = fmaf(mEc1, E, fmaf(pEc2, I, cE0));           \
            const float argIa   = fmaf(mIc3, E, fmaf(pIc4, I, cI0));           \
            const float sIa = rcpa(1.0f + ex2a(argIa));                        \
            const float Ina = fmaf(gIa, sIa, hIa);                             \
            /* A->B link coefficients — ready BEFORE sEa exists */             \
            const float K2e = mEc1 * gEa;                                      \
            float K1e = fmaf(mEc1, hEa, fmaf(pEc2, Ina, cE0));                 \
            /* matvec-A over E_{S-1} (summation order = validated R7) */       \
            const ulonglong2* ea =                                             \
                reinterpret_cast<const ulonglong2*>(ebuf[((PAR) + 3) & 3]);    \
            u64 a0 = pack2(base_ea, 0.0f);                                     \
            u64 a1 = 0ull, a2 = 0ull, a3 = 0ull;                               \
            _Pragma("unroll")                                                  \
            for (int j = 0; j < 17; j++) {                                     \
                ulonglong2 e = ea[j];                                          \
                if (j & 1) {                                                   \
                    a2 = ffma2(crow[2 * j],     e.x, a2);                      \
                    a3 = ffma2(crow[2 * j + 1], e.y, a3);                      \
                } else {                                                       \
                    a0 = ffma2(crow[2 * j],     e.x, a0);                      \
                    a1 = ffma2(crow[2 * j + 1], e.y, a1);                      \
                }                                                              \
            }                                                                  \
            /* matvec-B over E_S (independent; retires under tail-A) */        \
            const ulonglong2* eb2 =                                            \
                reinterpret_cast<const ulonglong2*>(ebuf[(PAR)]);              \
            u64 b0 = 0ull, b1 = 0ull, b2 = 0ull, b3 = 0ull;                    \
            _Pragma("unroll")                                                  \
            for (int j = 0; j < 17; j++) {                                     \
                ulonglong2 e = eb2[j];                                         \
                if (j & 1) {                                                   \
                    b2 = ffma2(crow[2 * j],     e.x, b2);                      \
                    b3 = ffma2(crow[2 * j + 1], e.y, b3);                      \
                } else {                                                       \
                    b0 = ffma2(crow[2 * j],     e.x, b0);                      \
                    b1 = ffma2(crow[2 * j + 1], e.y, b1);                      \
                }                                                              \
            }                                                                  \
            /* reduce-A -> tail-A MUFU chain */                                \
            u64 sv = fadd2(fadd2(a0, a1), fadd2(a2, a3));                      \
            float sx, sy;                                                      \
            unpk(sv, sx, sy);                                                  \
            const float argEa = sx + sy;                                       \
            const float sEa   = rcpa(1.0f + ex2a(argEa));                      \
            /* reduce-B + finish K1e (off-path, under tail-A's MUFU) */        \
            u64 tv = fadd2(fadd2(b0, b1), fadd2(b2, b3));                      \
            float tx, ty;                                                      \
            unpk(tv, tx, ty);                                                  \
            K1e += (tx + ty);              /* += connB */                      \
            /* CRITICAL LINK: one FMA from sEa into tail-B */                  \
            const float argEb = fmaf(K2e, sEa, K1e);                           \
            const float sEb   = rcpa(1.0f + ex2a(argEb));                      \
            /* off-path (in ex2/rcp shadow): Ena, publish, B coefficients */   \
            const float Ena = fmaf(gEa, sEa, hEa);                             \
            ebuf[((PAR) + 1) & 3][r] = Ena;        /* publish E_{S+1} */       \
            const float gEb = inv_te * (kE - Ena);                             \
            const float hEb = fmaf(-gEb, S0E, Ena * ce);                       \
            const float gIb = inv_ti * (kI - Ina);                             \
            const float hIb = fmaf(-gIb, S0I, Ina * ci);                       \
            const float argIb = fmaf(mIc3, Ena, fmaf(pIc4, Ina, cI0));         \
            const float sIb = rcpa(1.0f + ex2a(argIb));                        \
            const float Inb = fmaf(gIb, sIb, hIb);                             \
            /* close the chain */                                              \
            const float Enb = fmaf(gEb, sEb, hEb);                             \
            ebuf[((PAR) + 2) & 3][r] = Enb;        /* publish E_{S+2} */       \
            *reinterpret_cast<u64*>(                                           \
                &outbuf[((S) >> 5) & 1][r][(S) & (TILE - 1)]) =                \
                pack2(Ena - Ina, Enb - Inb);                                   \
            E = Enb;                                                           \
            I = Inb;                                                           \
        }                                                                      \
        __syncthreads();                                                       \
        if (wid == 3) {                                                        \
            FLUSH_STEP(S)                                                      \
            FLUSH_STEP((S) + 1)                                                \
        }                                                                      \
    }

    int s = 0;
    for (; s + 4 <= num_steps; s += 4) {
        BLOCK(0, s)
        BLOCK(2, s + 2)
    }
    if (s + 2 <= num_steps) {   // here s % 4 == 0
        BLOCK(0, s)
        s += 2;
    }
    if (s < num_steps) {        // odd leftover step (generic, runtime slot)
        if (r < NN) {
            const float gE = inv_te * (kE - E);
            const float hE = fmaf(-gE, S0E, E * ce);
            const float gI = inv_ti * (kI - I);
            const float hI = fmaf(-gI, S0I, I * ci);
            const float base_e = fmaf(mEc1, E, fmaf(pEc2, I, cE0));
            const float argI   = fmaf(mIc3, E, fmaf(pIc4, I, cI0));
            const float sIv = rcpa(1.0f + ex2a(argI));
            const float In  = fmaf(gI, sIv, hI);
            const ulonglong2* ea =
                reinterpret_cast<const ulonglong2*>(ebuf[(s + 3) & 3]);
            u64 a0 = pack2(base_e, 0.0f);
            u64 a1 = 0ull, a2 = 0ull, a3 = 0ull;
            #pragma unroll
            for (int j = 0; j < 17; j++) {
                ulonglong2 e = ea[j];
                if (j & 1) {
                    a2 = ffma2(crow[2 * j],     e.x, a2);
                    a3 = ffma2(crow[2 * j + 1], e.y, a3);
                } else {
                    a0 = ffma2(crow[2 * j],     e.x, a0);
                    a1 = ffma2(crow[2 * j + 1], e.y, a1);
                }
            }
            u64 sv = fadd2(fadd2(a0, a1), fadd2(a2, a3));
            float sx, sy;
            unpk(sv, sx, sy);
            const float argE = sx + sy;
            const float sEv  = rcpa(1.0f + ex2a(argE));
            const float En   = fmaf(gE, sEv, hE);
            outbuf[(s >> 5) & 1][r][s & (TILE - 1)] = En - In;
        }
        __syncthreads();
        s++;
    }
#undef BLOCK
#undef FLUSH_STEP

    // Epilogue: flush tiles the in-loop warp-3 flush couldn't cover
    // (last complete tile whose flush window fell off the end + partial tile).
    int start;
    if (num_steps < 36) start = 0;
    else                start = (((num_steps - 36) >> 5) << 5) + 32;
    for (int tb = start; tb < num_steps; tb += 32) {
        const int ftile = (tb >> 5) & 1;
        const int cnt   = num_steps - tb < 32 ? num_steps - tb : 32;
        for (int row = wid; row < NN; row += 4)
            if (lane < cnt)
                out[row * num_steps + tb + lane] = outbuf[ftile][row][lane];
    }
}

extern "C" void kernel_launch(void* const* d_in, const int* in_sizes, int n_in,
                              void* d_out, int out_size)
{
    const float* params = (const float*)d_in[0];
    const float* Cjk    = (const float*)d_in[1];
    const float* y0     = (const float*)d_in[2];
    // d_in[3] = Djk: unused by the reference computation.
    float* out = (float*)d_out;
    const int num_steps = out_size / NN;   // out is (N=68, num_steps)
    nmm_kernel<<<1, TPB>>>(params, Cjk, y0, out, num_steps);
}